// round 10
// baseline (speedup 1.0000x reference)
#include <cuda_runtime.h>

// Blur: depthwise 4x4 FIR (separable [1,3,3,1] ⊗ [1,3,3,1] / 16), pad (1,1).
// Input (4,128,513,513) f32 -> Output (4,128,512,512) f32.
//
// Round-10: R2's dense-load smem design with SPLIT staging (software pipeline,
// distance 1) at full register budget (8 CTAs/SM). Loop body:
//   STS row r (from regs loaded LAST iteration)  -> no load-latency exposure
//   LDG row r+1 into regs                        -> consumed next iteration
//   __syncwarp
//   consume row r: 2x LDS.128 -> horizontal FIR -> vertical ring -> STG.128
// The STS never waits on a fresh load, so the per-row ~500-cycle exposed
// DRAM stall of R2 disappears. 4-slot warp-private ring (>=1 syncwarp between
// any STS and the prior reads of that slot).

#define W_IN   513
#define H_IN   513
#define W_OUT  512
#define H_OUT  512
#define STRIP  64
#define BUFSZ  160      // idx 0..130 used; padded
#define NPLANE 512      // 4*128

__global__ __launch_bounds__(128, 8)
void blur_split_kernel(const float* __restrict__ in, float* __restrict__ out)
{
    __shared__ float sbuf[4][4][BUFSZ];   // [warp][ring slot][idx]  (10 KB)

    const int tid   = threadIdx.x;
    const int warp  = tid >> 5;
    const int lane  = tid & 31;
    const int plane = blockIdx.y;
    const int y0    = blockIdx.x * STRIP;
    const int wx0   = warp << 7;          // warp's first output col

    const float* ip = in  + (size_t)plane * (W_IN  * H_IN);
    float*       op = out + (size_t)plane * (W_OUT * H_OUT);

    // Window: buf[i] = in[row][wx0 - 1 + i], i in [0,131). Lane handles
    // idx = lane + 32k, k = 0..4. Only k=0 (left edge: warp0 lane0) and k=4
    // (idx >= 131 or right edge) can be out of range -> predicated loads.
    const int  goff = wx0 - 1 + lane;
    const bool m0   = (goff >= 0);
    const bool m4   = (lane < 3) && (goff + 128 < W_IN);

    float v0, v1, v2, v3, v4;             // regs holding the row in flight

    // Load row r into v0..v4 (pad rows -> zeros, warp-uniform branch).
    auto ldrow = [&](int r) {
        if ((unsigned)r < (unsigned)H_IN) {
            const float* __restrict__ rp = ip + (size_t)r * W_IN + goff;
            v0 = m0 ? __ldg(rp)       : 0.0f;
            v1 = __ldg(rp + 32);
            v2 = __ldg(rp + 64);
            v3 = __ldg(rp + 96);
            v4 = m4 ? __ldg(rp + 128) : 0.0f;
        } else {
            v0 = v1 = v2 = v3 = v4 = 0.0f;
        }
    };

    // Commit v0..v4 into a ring slot.
    auto strow = [&](int slot) {
        float* __restrict__ buf = &sbuf[warp][slot][0];
        buf[lane      ] = v0;
        buf[lane +  32] = v1;
        buf[lane +  64] = v2;
        buf[lane +  96] = v3;
        buf[lane + 128] = v4;
    };

    // Horizontal FIR: window buf[4l .. 4l+6] = in[x0-1 .. x0+5], x0 = wx0+4l.
    auto hcalc = [&](int slot) -> float4 {
        const float* __restrict__ buf = &sbuf[warp][slot][0];
        float4 a = *reinterpret_cast<const float4*>(buf + 4 * lane);       // x0-1..x0+2
        float4 c = *reinterpret_cast<const float4*>(buf + 4 * lane + 4);   // x0+3..x0+6
        float4 h;
        h.x = a.x + 3.0f * (a.y + a.z) + a.w;
        h.y = a.y + 3.0f * (a.z + a.w) + c.x;
        h.z = a.z + 3.0f * (a.w + c.x) + c.y;
        h.w = a.w + 3.0f * (c.x + c.y) + c.z;
        return h;
    };

    // Prologue (one-time load->store stalls are fine): rows y0-1..y0+1 staged,
    // row y0+2 left in registers for loop iteration 0.
    ldrow(y0 - 1); strow(0);
    ldrow(y0);     strow(1);
    ldrow(y0 + 1); strow(2);
    ldrow(y0 + 2);
    __syncwarp();
    float4 h[4];
    h[0] = hcalc(0);
    h[1] = hcalc(1);
    h[2] = hcalc(2);

    #pragma unroll 4
    for (int i = 0; i < STRIP; ++i) {
        strow((i + 3) & 3);       // commit row y0+2+i (loaded last iteration)
        ldrow(y0 + 3 + i);        // next row in flight; consumed next iteration
        __syncwarp();
        float4 hd = hcalc((i + 3) & 3);
        h[(i + 3) & 3] = hd;
        float4 ha = h[ i      & 3];
        float4 hb = h[(i + 1) & 3];
        float4 hc = h[(i + 2) & 3];

        float4 o;
        o.x = (ha.x + hd.x + 3.0f * (hb.x + hc.x)) * 0.0625f;
        o.y = (ha.y + hd.y + 3.0f * (hb.y + hc.y)) * 0.0625f;
        o.z = (ha.z + hd.z + 3.0f * (hb.z + hc.z)) * 0.0625f;
        o.w = (ha.w + hd.w + 3.0f * (hb.w + hc.w)) * 0.0625f;

        *reinterpret_cast<float4*>(op + (size_t)(y0 + i) * W_OUT + wx0 + 4 * lane) = o;
    }
}

extern "C" void kernel_launch(void* const* d_in, const int* in_sizes, int n_in,
                              void* d_out, int out_size)
{
    const float* in  = (const float*)d_in[0];
    float*       out = (float*)d_out;
    // d_in[1] is the 4x4 FIR buffer: fixed normalized [1,3,3,1] outer product
    // * factor^2 == ([1,3,3,1] ⊗ [1,3,3,1]) / 16, folded into the constants.

    dim3 grid(H_OUT / STRIP, NPLANE);   // (8, 512)
    blur_split_kernel<<<grid, 128>>>(in, out);
}

// round 11
// speedup vs baseline: 1.0864x; 1.0864x over previous
#include <cuda_runtime.h>

// Blur: depthwise 4x4 FIR (separable [1,3,3,1] ⊗ [1,3,3,1] / 16), pad (1,1).
// Input (4,128,513,513) f32 -> Output (4,128,512,512) f32.
//
// Round-11: fence-free shuffle kernel with TWO rows of loads batched per
// iteration (Little's-law fix: ~1KB per warp in flight instead of ~0.5KB).
// No smem, no __syncwarp: loads feed shuffles/FMA directly, so ptxas can
// keep both rows' 12 LDGs outstanding and overlap across iterations.
// Halo via shfl_up/down + 1 predicated edge load per row. Vertical FIR over
// a 5-deep rolling h window; two STG.128/thread per iteration.

#define W_IN   513
#define H_IN   513
#define W_OUT  512
#define H_OUT  512
#define STRIP  64
#define NPLANE 512      // 4*128
#define FULL   0xffffffffu

__global__ __launch_bounds__(128)
void blur_shfl2_kernel(const float* __restrict__ in, float* __restrict__ out)
{
    const int tid   = threadIdx.x;
    const int warp  = tid >> 5;
    const int lane  = tid & 31;
    const int plane = blockIdx.y;
    const int y0    = blockIdx.x * STRIP;
    const int wx0   = warp << 7;              // warp's first output col
    const int x0    = wx0 + (lane << 2);      // this thread's first output col

    const float* ip = in  + (size_t)plane * (W_IN  * H_IN);
    float*       op = out + (size_t)plane * (W_OUT * H_OUT);

    // Edge-load plan: lane0 -> col wx0-1, lane1 -> wx0+128, lane2 -> wx0+129.
    int  ecol;
    bool ep;
    if      (lane == 0) { ecol = wx0 - 1;   ep = (wx0 > 0); }
    else if (lane == 1) { ecol = wx0 + 128; ep = true; }             // <= 512 always
    else if (lane == 2) { ecol = wx0 + 129; ep = (wx0 + 129 < W_IN); }
    else                { ecol = wx0;       ep = false; }

    struct Row { float v0, v1, v2, v3, e; };

    // Issue the 5 loads of input row r (clamped address; caller masks pads).
    auto ldrow = [&](int r) -> Row {
        const int rc = min(max(r, 0), H_IN - 1);
        const float* __restrict__ rp = ip + (size_t)rc * W_IN;
        Row w;
        w.v0 = __ldg(rp + x0);
        w.v1 = __ldg(rp + x0 + 1);
        w.v2 = __ldg(rp + x0 + 2);
        w.v3 = __ldg(rp + x0 + 3);
        w.e  = ep ? __ldg(rp + ecol) : 0.0f;
        return w;
    };

    // Shuffle halo + horizontal FIR (rm zeroes pad rows).
    auto hcalc = [&](const Row& w, int r) -> float4 {
        const float rm = ((unsigned)r < (unsigned)H_IN) ? 1.0f : 0.0f;
        float e1 = __shfl_sync(FULL, w.e, 1);           // in[wx0+128]
        float e2 = __shfl_sync(FULL, w.e, 2);           // in[wx0+129]
        float t;
        t = __shfl_up_sync  (FULL, w.v3, 1); float xm1 = (lane ==  0) ? w.e : t; // in[x0-1]
        t = __shfl_down_sync(FULL, w.v0, 1); float xp4 = (lane == 31) ? e1  : t; // in[x0+4]
        t = __shfl_down_sync(FULL, w.v1, 1); float xp5 = (lane == 31) ? e2  : t; // in[x0+5]
        float4 h;
        h.x = (xm1  + 3.0f * (w.v0 + w.v1) + w.v2) * rm;
        h.y = (w.v0 + 3.0f * (w.v1 + w.v2) + w.v3) * rm;
        h.z = (w.v1 + 3.0f * (w.v2 + w.v3) + xp4 ) * rm;
        h.w = (w.v2 + 3.0f * (w.v3 + xp4 ) + xp5 ) * rm;
        return h;
    };

    // Prologue: rows y0-1, y0, y0+1 (batched loads, then FIR).
    Row wa = ldrow(y0 - 1);
    Row wb = ldrow(y0);
    Row wc = ldrow(y0 + 1);
    float4 ha = hcalc(wa, y0 - 1);
    float4 hb = hcalc(wb, y0);
    float4 hc = hcalc(wc, y0 + 1);

    #pragma unroll 4
    for (int i = 0; i < STRIP; i += 2) {
        // Batch both rows' loads before any consumption: ~12 independent LDGs.
        Row wd = ldrow(y0 + 2 + i);
        Row we = ldrow(y0 + 3 + i);
        float4 hd = hcalc(wd, y0 + 2 + i);
        float4 he = hcalc(we, y0 + 3 + i);

        float4 o0, o1;
        o0.x = (ha.x + hd.x + 3.0f * (hb.x + hc.x)) * 0.0625f;
        o0.y = (ha.y + hd.y + 3.0f * (hb.y + hc.y)) * 0.0625f;
        o0.z = (ha.z + hd.z + 3.0f * (hb.z + hc.z)) * 0.0625f;
        o0.w = (ha.w + hd.w + 3.0f * (hb.w + hc.w)) * 0.0625f;
        o1.x = (hb.x + he.x + 3.0f * (hc.x + hd.x)) * 0.0625f;
        o1.y = (hb.y + he.y + 3.0f * (hc.y + hd.y)) * 0.0625f;
        o1.z = (hb.z + he.z + 3.0f * (hc.z + hd.z)) * 0.0625f;
        o1.w = (hb.w + he.w + 3.0f * (hc.w + hd.w)) * 0.0625f;

        float* orow = op + (size_t)(y0 + i) * W_OUT + x0;
        *reinterpret_cast<float4*>(orow)         = o0;
        *reinterpret_cast<float4*>(orow + W_OUT) = o1;

        ha = hc; hb = hd; hc = he;        // advance vertical window by 2
    }
}

extern "C" void kernel_launch(void* const* d_in, const int* in_sizes, int n_in,
                              void* d_out, int out_size)
{
    const float* in  = (const float*)d_in[0];
    float*       out = (float*)d_out;
    // d_in[1] is the 4x4 FIR buffer: fixed normalized [1,3,3,1] outer product
    // * factor^2 == ([1,3,3,1] ⊗ [1,3,3,1]) / 16, folded into the constants.

    dim3 grid(H_OUT / STRIP, NPLANE);   // (8, 512)
    blur_shfl2_kernel<<<grid, 128>>>(in, out);
}